// round 14
// baseline (speedup 1.0000x reference)
#include <cuda_runtime.h>
#include <cuda_bf16.h>
#include <cstdint>
#include <math.h>

#define BATCH 256
#define SEQT  128
#define INP   512
#define HID   1024
#define NOUT  32
#define NG    4096   // 4*HID, interleaved gates: n = 4*j + g (0=i,1=f,2=cell,3=o)

// ---------------- scratch (device globals; no cudaMalloc allowed) ----------------
__device__ __nv_bfloat16 g_gx[(size_t)BATCH * SEQT * NG];    // input-proj preacts + bias (bf16)
__device__ __nv_bfloat16 g_xr[(size_t)BATCH * SEQT * INP];   // bf16 inputs
__device__ __nv_bfloat16 g_wi[(size_t)NG * INP];             // packed bf16 input weights
__device__ __nv_bfloat16 g_wh[(size_t)NG * HID];             // packed bf16 hidden weights
__device__ float         g_bias[NG];
__device__ __nv_bfloat16 g_h[2][BATCH * HID];                // double-buffered hidden state
__device__ unsigned      g_barg[2];                          // per-m-group barrier counters

// ---------------- helpers ----------------
__device__ __forceinline__ uint32_t smem_u32(const void* p) {
    return (uint32_t)__cvta_generic_to_shared(p);
}
__device__ __forceinline__ void cp16s(uint32_t dst, const void* src) {
    asm volatile("cp.async.cg.shared.global [%0], [%1], 16;" :: "r"(dst), "l"(src));
}
#define CP_COMMIT() asm volatile("cp.async.commit_group;" ::: "memory")
#define CP_WAIT0()  asm volatile("cp.async.wait_group 0;" ::: "memory")
#define CP_WAIT1()  asm volatile("cp.async.wait_group 1;" ::: "memory")

// 64B-row smem layout (BK=32 bf16), 16B chunk swizzle (R4-proven).
__device__ __forceinline__ uint32_t sw(int row, int c) {
    return (uint32_t)(row * 64 + ((c ^ ((row >> 1) & 3)) << 4));
}
// Persistent Wh smem: 2KB rows (K=1024 bf16), per-row chunk swizzle.
__device__ __forceinline__ uint32_t whsw(int row, int c) {
    return (uint32_t)(row * 2048 + ((c ^ (row & 7)) << 4));
}

__device__ __forceinline__ void ldsm4(uint32_t& r0, uint32_t& r1, uint32_t& r2, uint32_t& r3,
                                      uint32_t addr) {
    asm volatile("ldmatrix.sync.aligned.m8n8.x4.shared.b16 {%0,%1,%2,%3}, [%4];"
                 : "=r"(r0), "=r"(r1), "=r"(r2), "=r"(r3) : "r"(addr));
}

#define MMA_BF16(acc, a, b)                                                          \
    asm volatile(                                                                    \
        "mma.sync.aligned.m16n8k16.row.col.f32.bf16.bf16.f32 "                       \
        "{%0,%1,%2,%3},{%4,%5,%6,%7},{%8,%9},{%0,%1,%2,%3};"                         \
        : "+f"(acc[0]), "+f"(acc[1]), "+f"(acc[2]), "+f"(acc[3])                     \
        : "r"(a[0]), "r"(a[1]), "r"(a[2]), "r"(a[3]), "r"(b[0]), "r"(b[1]))

__device__ __forceinline__ float sigm(float x)   { return 1.f / (1.f + __expf(-x)); }
__device__ __forceinline__ float tanhff(float x) { return 1.f - 2.f / (__expf(2.f * x) + 1.f); }

// pack 4 floats -> 4 bf16 (8 bytes), same per-element rounding as before
__device__ __forceinline__ uint2 bf4(float4 v) {
    __nv_bfloat162 lo = __float22bfloat162_rn(make_float2(v.x, v.y));
    __nv_bfloat162 hi = __float22bfloat162_rn(make_float2(v.z, v.w));
    uint2 r;
    r.x = *reinterpret_cast<uint32_t*>(&lo);
    r.y = *reinterpret_cast<uint32_t*>(&hi);
    return r;
}

// ---------------- prep (2 kernels so k_steps is the 4th launch for ncu) ----------------
// Vectorized: float4 loads, 8-byte bf16x4 stores (bit-identical element rounding).
__global__ void k_prep0(const float* __restrict__ x,
                        const float* __restrict__ wii, const float* __restrict__ wif,
                        const float* __restrict__ wic, const float* __restrict__ wio,
                        const float* __restrict__ whi, const float* __restrict__ whf,
                        const float* __restrict__ whc, const float* __restrict__ who) {
    const size_t stride = (size_t)gridDim.x * blockDim.x;
    const size_t t0 = (size_t)blockIdx.x * blockDim.x + threadIdx.x;

    // x: 16.8M elems = 4.2M float4s
    for (size_t i = t0; i < (size_t)BATCH * SEQT * INP / 4; i += stride) {
        float4 v = reinterpret_cast<const float4*>(x)[i];
        reinterpret_cast<uint2*>(g_xr)[i] = bf4(v);
    }
    // wi pack: 4 consecutive k's share row j of matrix g
    for (size_t i = t0; i < (size_t)NG * INP / 4; i += stride) {
        size_t e = i * 4;
        int n = (int)(e / INP), k = (int)(e % INP);
        int g = n & 3, j = n >> 2;
        const float* w = (g == 0) ? wii : (g == 1) ? wif : (g == 2) ? wic : wio;
        float4 v = *reinterpret_cast<const float4*>(&w[(size_t)j * INP + k]);
        reinterpret_cast<uint2*>(g_wi)[i] = bf4(v);
    }
    // wh pack
    for (size_t i = t0; i < (size_t)NG * HID / 4; i += stride) {
        size_t e = i * 4;
        int n = (int)(e / HID), k = (int)(e % HID);
        int g = n & 3, j = n >> 2;
        const float* w = (g == 0) ? whi : (g == 1) ? whf : (g == 2) ? whc : who;
        float4 v = *reinterpret_cast<const float4*>(&w[(size_t)j * HID + k]);
        reinterpret_cast<uint2*>(g_wh)[i] = bf4(v);
    }
}

__global__ void k_prep1(const float* bii, const float* bhi, const float* bif, const float* bhf,
                        const float* bic, const float* bhc, const float* bio, const float* bho) {
    int i = blockIdx.x * blockDim.x + threadIdx.x;
    if (i < BATCH * HID / 4)
        reinterpret_cast<uint2*>(g_h[0])[i] = make_uint2(0u, 0u);
    if (i < NG) {
        int g = i & 3, j = i >> 2;
        float v;
        if (g == 0)      v = bii[j] + bhi[j];
        else if (g == 1) v = bif[j] + bhf[j];
        else if (g == 2) v = bic[j] + bhc[j];
        else             v = bio[j] + bho[j];
        g_bias[i] = v;
    }
    if (i < 2) g_barg[i] = 0u;
}

// ============================================================================
// Input GEMM (R12, unchanged): g_gx = bf16(Xr @ Wi^T + bias)
// CTA tile 128 x 128, K=512, BK=32, 3-stage cp.async, 1 barrier/slab.
// 8 warps as 4m x 2n; warp tile 32x64. Grid (32 n, 256 m). 48KB smem.
// ============================================================================
static const int X_SMEM = 49152;

__global__ __launch_bounds__(256, 1) void k_gemm_x() {
    extern __shared__ char smem[];
    const uint32_t sb = smem_u32(smem);
    const int tid = threadIdx.x, lane = tid & 31, wid = tid >> 5;
    const int wm = wid & 3, wn = wid >> 2;
    const int n0 = blockIdx.x * 128, m0 = blockIdx.y * 128;

    float acc[2][8][4];
#pragma unroll
    for (int mi = 0; mi < 2; mi++)
#pragma unroll
        for (int ni = 0; ni < 8; ni++)
#pragma unroll
            for (int q = 0; q < 4; q++) acc[mi][ni][q] = 0.f;

    auto load_slab = [&](int s) {
        const uint32_t ab = sb + (uint32_t)(s % 3) * 16384u;
        const int k0 = s * 32;
#pragma unroll
        for (int i = 0; i < 2; i++) {
            int q = tid + i * 256, row = q >> 2, c = q & 3;
            cp16s(ab + sw(row, c), g_xr + (size_t)(m0 + row) * INP + k0 + c * 8);
        }
#pragma unroll
        for (int i = 0; i < 2; i++) {
            int q = tid + i * 256, row = q >> 2, c = q & 3;
            cp16s(ab + 8192u + sw(row, c), g_wi + (size_t)(n0 + row) * INP + k0 + c * 8);
        }
    };

    const int KT = INP / 32;
    load_slab(0); CP_COMMIT();
    load_slab(1); CP_COMMIT();
    for (int kt = 0; kt < KT; kt++) {
        if (kt + 1 < KT) CP_WAIT1(); else CP_WAIT0();
        __syncthreads();
        if (kt + 2 < KT) { load_slab(kt + 2); CP_COMMIT(); }
        const uint32_t ab = sb + (uint32_t)(kt % 3) * 16384u;
        const uint32_t bb = ab + 8192u;
#pragma unroll
        for (int ks = 0; ks < 2; ks++) {
            uint32_t a[2][4];
#pragma unroll
            for (int mi = 0; mi < 2; mi++) {
                int row = wm * 32 + mi * 16 + (lane & 15);
                int c = 2 * ks + (lane >> 4);
                ldsm4(a[mi][0], a[mi][1], a[mi][2], a[mi][3], ab + sw(row, c));
            }
            uint32_t b[8][2];
#pragma unroll
            for (int nt = 0; nt < 4; nt++) {
                int row = wn * 64 + nt * 16 + ((lane >> 4) << 3) + (lane & 7);
                int c = 2 * ks + ((lane >> 3) & 1);
                ldsm4(b[2 * nt][0], b[2 * nt][1], b[2 * nt + 1][0], b[2 * nt + 1][1],
                      bb + sw(row, c));
            }
#pragma unroll
            for (int mi = 0; mi < 2; mi++)
#pragma unroll
                for (int ni = 0; ni < 8; ni++) MMA_BF16(acc[mi][ni], a[mi], b[ni]);
        }
    }

    const int lr = lane >> 2, lc = lane & 3;
#pragma unroll
    for (int mi = 0; mi < 2; mi++)
#pragma unroll
        for (int ni = 0; ni < 8; ni++) {
            int r = wm * 32 + mi * 16 + lr;
            int cc = wn * 64 + ni * 8 + 2 * lc;
            int n = n0 + cc;
            float b0 = g_bias[n], b1 = g_bias[n + 1];
            __nv_bfloat162 v0 = __float22bfloat162_rn(
                make_float2(acc[mi][ni][0] + b0, acc[mi][ni][1] + b1));
            __nv_bfloat162 v1 = __float22bfloat162_rn(
                make_float2(acc[mi][ni][2] + b0, acc[mi][ni][3] + b1));
            *reinterpret_cast<__nv_bfloat162*>(&g_gx[(size_t)(m0 + r) * NG + n])     = v0;
            *reinterpret_cast<__nv_bfloat162*>(&g_gx[(size_t)(m0 + r + 8) * NG + n]) = v1;
        }
}

// ============================================================================
// Persistent step kernel: R13 byte-identical (R12 mainloop/epilogue, release/
// acquire grid barrier, gx[t+1] prefetch overlapping the barrier wait).
// Smem: [0,128K) Wh | [128K,+24K) A | [155648,+18432) gx | [174080,+33280) pre.
// ============================================================================
static const int A_OFF   = 131072;
static const int GX_OFF  = 131072 + 3 * 8192;            // 155648
static const int GX_STRIDE_B = 144;                      // 64 bf16 = 128B + 16B pad
static const int PRE_OFF = GX_OFF + 128 * GX_STRIDE_B;   // 174080
static const int S_SMEM  = PRE_OFF + 33280;              // 207360

__global__ __launch_bounds__(256, 1) void k_steps(const float* __restrict__ wfc,
                                                  float* __restrict__ out) {
    extern __shared__ char smem[];
    const uint32_t sb = smem_u32(smem);
    const int tid = threadIdx.x, lane = tid & 31, wid = tid >> 5;
    const int wm = wid & 3, wn = wid >> 2;
    const int n0 = blockIdx.x * 64, m0 = blockIdx.y * 128;
    const int grp = blockIdx.y;

    // ---- load Wh slice (64 rows x 1024 bf16 = 128KB) into persistent smem ----
#pragma unroll
    for (int i = 0; i < 32; i++) {
        int idx = tid + i * 256;            // 8192 16B-chunks
        int row = idx >> 7, c = idx & 127;
        cp16s(sb + whsw(row, c), g_wh + (size_t)(n0 + row) * HID + c * 8);
    }
    CP_COMMIT();

    auto prefetch_gx = [&](int t) {
#pragma unroll
        for (int i = 0; i < 4; i++) {       // 1024 16B-chunks, 4/thread
            int idx = tid + i * 256;
            int row = idx >> 3, c = idx & 7;
            cp16s(sb + GX_OFF + (uint32_t)(row * GX_STRIDE_B + c * 16),
                  &g_gx[((size_t)(m0 + row) * SEQT + t) * NG + n0 + c * 8]);
        }
    };

    // gx[0] prefetch (own group; completes under the first mainloop wait)
    prefetch_gx(0); CP_COMMIT();

    float creg[8];
#pragma unroll
    for (int q = 0; q < 8; q++) creg[q] = 0.f;

    float* pre = (float*)(smem + PRE_OFF);
    const int KT = HID / 32;   // 32

    for (int t = 0; t < SEQT; t++) {
        const __nv_bfloat16* __restrict__ hin = g_h[t & 1];
        __nv_bfloat16* __restrict__ hout = g_h[(t + 1) & 1];

        float acc[2][4][4];
#pragma unroll
        for (int mi = 0; mi < 2; mi++)
#pragma unroll
            for (int ni = 0; ni < 4; ni++)
#pragma unroll
                for (int q = 0; q < 4; q++) acc[mi][ni][q] = 0.f;

        auto load_slab = [&](int s) {
            const uint32_t ab = sb + A_OFF + (uint32_t)(s % 3) * 8192u;
            const int k0 = s * 32;
#pragma unroll
            for (int i = 0; i < 2; i++) {   // A: 128 rows x 4 chunks
                int q = tid + i * 256, row = q >> 2, c = q & 3;
                cp16s(ab + sw(row, c), hin + (size_t)(m0 + row) * HID + k0 + c * 8);
            }
        };

        load_slab(0); CP_COMMIT();
        load_slab(1); CP_COMMIT();

        for (int kt = 0; kt < KT; kt++) {
            if (kt + 1 < KT) CP_WAIT1(); else CP_WAIT0();
            __syncthreads();
            if (kt + 2 < KT) { load_slab(kt + 2); CP_COMMIT(); }
            const uint32_t ab = sb + A_OFF + (uint32_t)(kt % 3) * 8192u;
#pragma unroll
            for (int ks = 0; ks < 2; ks++) {
                uint32_t a[2][4];
#pragma unroll
                for (int mi = 0; mi < 2; mi++) {
                    int row = wm * 32 + mi * 16 + (lane & 15);
                    int c = 2 * ks + (lane >> 4);
                    ldsm4(a[mi][0], a[mi][1], a[mi][2], a[mi][3], ab + sw(row, c));
                }
                uint32_t b[4][2];
#pragma unroll
                for (int nt = 0; nt < 2; nt++) {
                    int row = wn * 32 + nt * 16 + ((lane >> 4) << 3) + (lane & 7);
                    int gc = kt * 4 + 2 * ks + ((lane >> 3) & 1);
                    ldsm4(b[2 * nt][0], b[2 * nt][1], b[2 * nt + 1][0], b[2 * nt + 1][1],
                          sb + whsw(row, gc));
                }
#pragma unroll
                for (int mi = 0; mi < 2; mi++)
#pragma unroll
                    for (int ni = 0; ni < 4; ni++) MMA_BF16(acc[mi][ni], a[mi], b[ni]);
            }
        }

        // scatter acc -> pre-tile [128][64], stride 65
        const int lr = lane >> 2, lc = lane & 3;
#pragma unroll
        for (int mi = 0; mi < 2; mi++)
#pragma unroll
            for (int ni = 0; ni < 4; ni++) {
                int r = wm * 32 + mi * 16 + lr;
                int cc = wn * 32 + ni * 8 + 2 * lc;
                pre[r * 65 + cc]           = acc[mi][ni][0];
                pre[r * 65 + cc + 1]       = acc[mi][ni][1];
                pre[(r + 8) * 65 + cc]     = acc[mi][ni][2];
                pre[(r + 8) * 65 + cc + 1] = acc[mi][ni][3];
            }
        __syncthreads();

        // fused LSTM elementwise: 8 (b,j) pairs per thread (gx bf16 from smem)
#pragma unroll
        for (int s = 0; s < 8; s++) {
            int p = s * 256 + tid;
            int r = p >> 4, jj = p & 15;
            int b = m0 + r;
            const __nv_bfloat162* g2 = reinterpret_cast<const __nv_bfloat162*>(
                smem + GX_OFF + r * GX_STRIDE_B + 8 * jj);
            float2 ga = __bfloat1622float2(g2[0]);
            float2 gb = __bfloat1622float2(g2[1]);
            float p0 = pre[r * 65 + 4 * jj + 0] + ga.x;
            float p1 = pre[r * 65 + 4 * jj + 1] + ga.y;
            float p2 = pre[r * 65 + 4 * jj + 2] + gb.x;
            float p3 = pre[r * 65 + 4 * jj + 3] + gb.y;
            float ig = sigm(p0);
            float fg = sigm(p1);
            float gg = tanhff(p2);
            float og = sigm(p3);
            float cn = fg * creg[s] + ig * gg;
            creg[s] = cn;
            hout[b * HID + (n0 >> 2) + jj] = __float2bfloat16_rn(og * tanhff(cn));
        }

        // ---- per-m-group grid barrier: bar.sync -> release-add -> acquire poll ----
        __syncthreads();                    // all h stores issued; gxs reads done
        if (t + 1 < SEQT) prefetch_gx(t + 1);   // h-independent; overlaps the wait
        CP_COMMIT();
        if (tid == 0) {
            unsigned target = (unsigned)(t + 1) * 64u;
            asm volatile("red.release.gpu.global.add.u32 [%0], %1;"
                         :: "l"(&g_barg[grp]), "r"(1u) : "memory");
            unsigned v;
            do {
                asm volatile("ld.acquire.gpu.global.u32 %0, [%1];"
                             : "=r"(v) : "l"(&g_barg[grp]) : "memory");
            } while (v < target);
        }
        __syncthreads();
    }

    // ======== fused final FC + log_softmax (after t=127 group barrier) ========
    // Each CTA handles 2 batch rows of its own m-group: b = m0 + 2*bx + {0,1}.
    {
        const __nv_bfloat16* __restrict__ hf = g_h[0];   // t=127 wrote buffer 0
        float* hrow = (float*)(smem + A_OFF);            // 2 x 1024 f32 = 8KB
        float* lg   = (float*)(smem + A_OFF + 8192);     // 2 x 32 logits
        const int bx = blockIdx.x;
#pragma unroll
        for (int rr = 0; rr < 2; rr++) {
            int b = m0 + 2 * bx + rr;
            for (int i = tid; i < HID; i += 256)
                hrow[rr * 1024 + i] = __bfloat162float(hf[(size_t)b * HID + i]);
        }
        __syncthreads();

        // 8 warps x 4 outputs = 32 outputs, each for both rows
#pragma unroll
        for (int rr = 0; rr < 2; rr++) {
#pragma unroll
            for (int oo = 0; oo < 4; oo++) {
                int o = wid * 4 + oo;
                const float* w = wfc + (size_t)o * HID;
                float s = 0.f;
                for (int k = lane; k < HID; k += 32) s += hrow[rr * 1024 + k] * w[k];
#pragma unroll
                for (int off = 16; off; off >>= 1) s += __shfl_xor_sync(0xffffffffu, s, off);
                if (lane == 0) lg[rr * 32 + o] = s;
            }
        }
        __syncthreads();

        if (tid < 64) {                     // warp 0 -> row 0, warp 1 -> row 1
            int rr = tid >> 5, oi = tid & 31;
            float l = lg[rr * 32 + oi];
            float m = l;
#pragma unroll
            for (int off = 16; off; off >>= 1) m = fmaxf(m, __shfl_xor_sync(0xffffffffu, m, off));
            float e = expf(l - m);
            float se = e;
#pragma unroll
            for (int off = 16; off; off >>= 1) se += __shfl_xor_sync(0xffffffffu, se, off);
            out[(m0 + 2 * bx + rr) * NOUT + oi] = l - m - logf(se);
        }
    }
}

// ---------------- launch ----------------
extern "C" void kernel_launch(void* const* d_in, const int* in_sizes, int n_in,
                              void* d_out, int out_size) {
    const float* x    = (const float*)d_in[0];
    const float* w_ii = (const float*)d_in[1];
    const float* w_hi = (const float*)d_in[2];
    const float* b_ii = (const float*)d_in[3];
    const float* b_hi = (const float*)d_in[4];
    const float* w_if = (const float*)d_in[5];
    const float* w_hf = (const float*)d_in[6];
    const float* b_if = (const float*)d_in[7];
    const float* b_hf = (const float*)d_in[8];
    const float* w_io = (const float*)d_in[9];
    const float* w_ho = (const float*)d_in[10];
    const float* b_io = (const float*)d_in[11];
    const float* b_ho = (const float*)d_in[12];
    const float* w_ic = (const float*)d_in[13];
    const float* w_hc = (const float*)d_in[14];
    const float* b_ic = (const float*)d_in[15];
    const float* b_hc = (const float*)d_in[16];
    const float* w_fc = (const float*)d_in[17];

    cudaFuncSetAttribute(k_gemm_x, cudaFuncAttributeMaxDynamicSharedMemorySize, X_SMEM);
    cudaFuncSetAttribute(k_steps,  cudaFuncAttributeMaxDynamicSharedMemorySize, S_SMEM);

    k_prep0<<<1024, 256>>>(x, w_ii, w_if, w_ic, w_io, w_hi, w_hf, w_hc, w_ho);
    k_prep1<<<256, 256>>>(b_ii, b_hi, b_if, b_hf, b_ic, b_hc, b_io, b_ho);

    k_gemm_x<<<dim3(32, 256), 256, X_SMEM>>>();

    k_steps<<<dim3(64, 2), 256, S_SMEM>>>(w_fc, (float*)d_out);
}

// round 15
// speedup vs baseline: 1.0533x; 1.0533x over previous
#include <cuda_runtime.h>
#include <cuda_bf16.h>
#include <cstdint>
#include <math.h>

#define BATCH 256
#define SEQT  128
#define INP   512
#define HID   1024
#define NOUT  32
#define NG    4096   // 4*HID, interleaved gates: n = 4*j + g (0=i,1=f,2=cell,3=o)

// ---------------- scratch (device globals; no cudaMalloc allowed) ----------------
__device__ __nv_bfloat16 g_gx[(size_t)BATCH * SEQT * NG];    // input-proj preacts + bias (bf16)
__device__ __nv_bfloat16 g_xr[(size_t)BATCH * SEQT * INP];   // bf16 inputs
__device__ __nv_bfloat16 g_wi[(size_t)NG * INP];             // packed bf16 input weights
__device__ __nv_bfloat16 g_wh[(size_t)NG * HID];             // packed bf16 hidden weights
__device__ float         g_bias[NG];
__device__ __nv_bfloat16 g_h[2][BATCH * HID];                // double-buffered hidden state
__device__ unsigned      g_barg[2];                          // per-m-group barrier counters

// ---------------- helpers ----------------
__device__ __forceinline__ uint32_t smem_u32(const void* p) {
    return (uint32_t)__cvta_generic_to_shared(p);
}
__device__ __forceinline__ void cp16s(uint32_t dst, const void* src) {
    asm volatile("cp.async.cg.shared.global [%0], [%1], 16;" :: "r"(dst), "l"(src));
}
#define CP_COMMIT() asm volatile("cp.async.commit_group;" ::: "memory")
#define CP_WAIT0()  asm volatile("cp.async.wait_group 0;" ::: "memory")
#define CP_WAIT1()  asm volatile("cp.async.wait_group 1;" ::: "memory")

// 64B-row smem layout (BK=32 bf16), 16B chunk swizzle (R4-proven).
__device__ __forceinline__ uint32_t sw(int row, int c) {
    return (uint32_t)(row * 64 + ((c ^ ((row >> 1) & 3)) << 4));
}
// Persistent Wh smem: 2KB rows (K=1024 bf16), per-row chunk swizzle.
__device__ __forceinline__ uint32_t whsw(int row, int c) {
    return (uint32_t)(row * 2048 + ((c ^ (row & 7)) << 4));
}

__device__ __forceinline__ void ldsm4(uint32_t& r0, uint32_t& r1, uint32_t& r2, uint32_t& r3,
                                      uint32_t addr) {
    asm volatile("ldmatrix.sync.aligned.m8n8.x4.shared.b16 {%0,%1,%2,%3}, [%4];"
                 : "=r"(r0), "=r"(r1), "=r"(r2), "=r"(r3) : "r"(addr));
}

#define MMA_BF16(acc, a, b)                                                          \
    asm volatile(                                                                    \
        "mma.sync.aligned.m16n8k16.row.col.f32.bf16.bf16.f32 "                       \
        "{%0,%1,%2,%3},{%4,%5,%6,%7},{%8,%9},{%0,%1,%2,%3};"                         \
        : "+f"(acc[0]), "+f"(acc[1]), "+f"(acc[2]), "+f"(acc[3])                     \
        : "r"(a[0]), "r"(a[1]), "r"(a[2]), "r"(a[3]), "r"(b[0]), "r"(b[1]))

__device__ __forceinline__ float sigm(float x)   { return 1.f / (1.f + __expf(-x)); }
__device__ __forceinline__ float tanhff(float x) { return 1.f - 2.f / (__expf(2.f * x) + 1.f); }

// ---------------- prep (2 kernels so k_steps is the 4th launch for ncu) ----------------
__global__ void k_prep0(const float* __restrict__ x,
                        const float* __restrict__ wii, const float* __restrict__ wif,
                        const float* __restrict__ wic, const float* __restrict__ wio,
                        const float* __restrict__ whi, const float* __restrict__ whf,
                        const float* __restrict__ whc, const float* __restrict__ who) {
    const size_t stride = (size_t)gridDim.x * blockDim.x;
    const size_t t0 = (size_t)blockIdx.x * blockDim.x + threadIdx.x;
    for (size_t i = t0; i < (size_t)BATCH * SEQT * INP; i += stride)
        g_xr[i] = __float2bfloat16_rn(x[i]);
    for (size_t i = t0; i < (size_t)NG * INP; i += stride) {
        int n = (int)(i / INP), k = (int)(i % INP);
        int g = n & 3, j = n >> 2;
        const float* w = (g == 0) ? wii : (g == 1) ? wif : (g == 2) ? wic : wio;
        g_wi[i] = __float2bfloat16_rn(w[(size_t)j * INP + k]);
    }
    for (size_t i = t0; i < (size_t)NG * HID; i += stride) {
        int n = (int)(i / HID), k = (int)(i % HID);
        int g = n & 3, j = n >> 2;
        const float* w = (g == 0) ? whi : (g == 1) ? whf : (g == 2) ? whc : who;
        g_wh[i] = __float2bfloat16_rn(w[(size_t)j * HID + k]);
    }
}

__global__ void k_prep1(const float* bii, const float* bhi, const float* bif, const float* bhf,
                        const float* bic, const float* bhc, const float* bio, const float* bho) {
    int i = blockIdx.x * blockDim.x + threadIdx.x;
    if (i < BATCH * HID) g_h[0][i] = __float2bfloat16_rn(0.f);
    if (i < NG) {
        int g = i & 3, j = i >> 2;
        float v;
        if (g == 0)      v = bii[j] + bhi[j];
        else if (g == 1) v = bif[j] + bhf[j];
        else if (g == 2) v = bic[j] + bhc[j];
        else             v = bio[j] + bho[j];
        g_bias[i] = v;
    }
    if (i < 2) g_barg[i] = 0u;
}

// ============================================================================
// Input GEMM (R12, unchanged): g_gx = bf16(Xr @ Wi^T + bias)
// CTA tile 128 x 128, K=512, BK=32, 3-stage cp.async, 1 barrier/slab.
// 8 warps as 4m x 2n; warp tile 32x64. Grid (32 n, 256 m). 48KB smem.
// ============================================================================
static const int X_SMEM = 49152;

__global__ __launch_bounds__(256, 1) void k_gemm_x() {
    extern __shared__ char smem[];
    const uint32_t sb = smem_u32(smem);
    const int tid = threadIdx.x, lane = tid & 31, wid = tid >> 5;
    const int wm = wid & 3, wn = wid >> 2;
    const int n0 = blockIdx.x * 128, m0 = blockIdx.y * 128;

    float acc[2][8][4];
#pragma unroll
    for (int mi = 0; mi < 2; mi++)
#pragma unroll
        for (int ni = 0; ni < 8; ni++)
#pragma unroll
            for (int q = 0; q < 4; q++) acc[mi][ni][q] = 0.f;

    auto load_slab = [&](int s) {
        const uint32_t ab = sb + (uint32_t)(s % 3) * 16384u;
        const int k0 = s * 32;
#pragma unroll
        for (int i = 0; i < 2; i++) {
            int q = tid + i * 256, row = q >> 2, c = q & 3;
            cp16s(ab + sw(row, c), g_xr + (size_t)(m0 + row) * INP + k0 + c * 8);
        }
#pragma unroll
        for (int i = 0; i < 2; i++) {
            int q = tid + i * 256, row = q >> 2, c = q & 3;
            cp16s(ab + 8192u + sw(row, c), g_wi + (size_t)(n0 + row) * INP + k0 + c * 8);
        }
    };

    const int KT = INP / 32;
    load_slab(0); CP_COMMIT();
    load_slab(1); CP_COMMIT();
    for (int kt = 0; kt < KT; kt++) {
        if (kt + 1 < KT) CP_WAIT1(); else CP_WAIT0();
        __syncthreads();
        if (kt + 2 < KT) { load_slab(kt + 2); CP_COMMIT(); }
        const uint32_t ab = sb + (uint32_t)(kt % 3) * 16384u;
        const uint32_t bb = ab + 8192u;
#pragma unroll
        for (int ks = 0; ks < 2; ks++) {
            uint32_t a[2][4];
#pragma unroll
            for (int mi = 0; mi < 2; mi++) {
                int row = wm * 32 + mi * 16 + (lane & 15);
                int c = 2 * ks + (lane >> 4);
                ldsm4(a[mi][0], a[mi][1], a[mi][2], a[mi][3], ab + sw(row, c));
            }
            uint32_t b[8][2];
#pragma unroll
            for (int nt = 0; nt < 4; nt++) {
                int row = wn * 64 + nt * 16 + ((lane >> 4) << 3) + (lane & 7);
                int c = 2 * ks + ((lane >> 3) & 1);
                ldsm4(b[2 * nt][0], b[2 * nt][1], b[2 * nt + 1][0], b[2 * nt + 1][1],
                      bb + sw(row, c));
            }
#pragma unroll
            for (int mi = 0; mi < 2; mi++)
#pragma unroll
                for (int ni = 0; ni < 8; ni++) MMA_BF16(acc[mi][ni], a[mi], b[ni]);
        }
    }

    const int lr = lane >> 2, lc = lane & 3;
#pragma unroll
    for (int mi = 0; mi < 2; mi++)
#pragma unroll
        for (int ni = 0; ni < 8; ni++) {
            int r = wm * 32 + mi * 16 + lr;
            int cc = wn * 64 + ni * 8 + 2 * lc;
            int n = n0 + cc;
            float b0 = g_bias[n], b1 = g_bias[n + 1];
            __nv_bfloat162 v0 = __float22bfloat162_rn(
                make_float2(acc[mi][ni][0] + b0, acc[mi][ni][1] + b1));
            __nv_bfloat162 v1 = __float22bfloat162_rn(
                make_float2(acc[mi][ni][2] + b0, acc[mi][ni][3] + b1));
            *reinterpret_cast<__nv_bfloat162*>(&g_gx[(size_t)(m0 + r) * NG + n])     = v0;
            *reinterpret_cast<__nv_bfloat162*>(&g_gx[(size_t)(m0 + r + 8) * NG + n]) = v1;
        }
}

// ============================================================================
// Persistent step kernel (R13, unchanged): R12 mainloop/epilogue, release/
// acquire grid barrier, gx[t+1] prefetch overlapping the barrier wait.
// Smem: [0,128K) Wh | [128K,+24K) A | [155648,+18432) gx | [174080,+33280) pre.
// ============================================================================
static const int A_OFF   = 131072;
static const int GX_OFF  = 131072 + 3 * 8192;            // 155648
static const int GX_STRIDE_B = 144;                      // 64 bf16 = 128B + 16B pad
static const int PRE_OFF = GX_OFF + 128 * GX_STRIDE_B;   // 174080
static const int S_SMEM  = PRE_OFF + 33280;              // 207360

__global__ __launch_bounds__(256, 1) void k_steps(const float* __restrict__ wfc,
                                                  float* __restrict__ out) {
    extern __shared__ char smem[];
    const uint32_t sb = smem_u32(smem);
    const int tid = threadIdx.x, lane = tid & 31, wid = tid >> 5;
    const int wm = wid & 3, wn = wid >> 2;
    const int n0 = blockIdx.x * 64, m0 = blockIdx.y * 128;
    const int grp = blockIdx.y;

    // ---- load Wh slice (64 rows x 1024 bf16 = 128KB) into persistent smem ----
#pragma unroll
    for (int i = 0; i < 32; i++) {
        int idx = tid + i * 256;            // 8192 16B-chunks
        int row = idx >> 7, c = idx & 127;
        cp16s(sb + whsw(row, c), g_wh + (size_t)(n0 + row) * HID + c * 8);
    }
    CP_COMMIT();

    auto prefetch_gx = [&](int t) {
#pragma unroll
        for (int i = 0; i < 4; i++) {       // 1024 16B-chunks, 4/thread
            int idx = tid + i * 256;
            int row = idx >> 3, c = idx & 7;
            cp16s(sb + GX_OFF + (uint32_t)(row * GX_STRIDE_B + c * 16),
                  &g_gx[((size_t)(m0 + row) * SEQT + t) * NG + n0 + c * 8]);
        }
    };

    // gx[0] prefetch (own group; completes under the first mainloop wait)
    prefetch_gx(0); CP_COMMIT();

    float creg[8];
#pragma unroll
    for (int q = 0; q < 8; q++) creg[q] = 0.f;

    float* pre = (float*)(smem + PRE_OFF);
    const int KT = HID / 32;   // 32

    for (int t = 0; t < SEQT; t++) {
        const __nv_bfloat16* __restrict__ hin = g_h[t & 1];
        __nv_bfloat16* __restrict__ hout = g_h[(t + 1) & 1];

        float acc[2][4][4];
#pragma unroll
        for (int mi = 0; mi < 2; mi++)
#pragma unroll
            for (int ni = 0; ni < 4; ni++)
#pragma unroll
                for (int q = 0; q < 4; q++) acc[mi][ni][q] = 0.f;

        auto load_slab = [&](int s) {
            const uint32_t ab = sb + A_OFF + (uint32_t)(s % 3) * 8192u;
            const int k0 = s * 32;
#pragma unroll
            for (int i = 0; i < 2; i++) {   // A: 128 rows x 4 chunks
                int q = tid + i * 256, row = q >> 2, c = q & 3;
                cp16s(ab + sw(row, c), hin + (size_t)(m0 + row) * HID + k0 + c * 8);
            }
        };

        load_slab(0); CP_COMMIT();
        load_slab(1); CP_COMMIT();

        for (int kt = 0; kt < KT; kt++) {
            if (kt + 1 < KT) CP_WAIT1(); else CP_WAIT0();
            __syncthreads();
            if (kt + 2 < KT) { load_slab(kt + 2); CP_COMMIT(); }
            const uint32_t ab = sb + A_OFF + (uint32_t)(kt % 3) * 8192u;
#pragma unroll
            for (int ks = 0; ks < 2; ks++) {
                uint32_t a[2][4];
#pragma unroll
                for (int mi = 0; mi < 2; mi++) {
                    int row = wm * 32 + mi * 16 + (lane & 15);
                    int c = 2 * ks + (lane >> 4);
                    ldsm4(a[mi][0], a[mi][1], a[mi][2], a[mi][3], ab + sw(row, c));
                }
                uint32_t b[4][2];
#pragma unroll
                for (int nt = 0; nt < 2; nt++) {
                    int row = wn * 32 + nt * 16 + ((lane >> 4) << 3) + (lane & 7);
                    int gc = kt * 4 + 2 * ks + ((lane >> 3) & 1);
                    ldsm4(b[2 * nt][0], b[2 * nt][1], b[2 * nt + 1][0], b[2 * nt + 1][1],
                          sb + whsw(row, gc));
                }
#pragma unroll
                for (int mi = 0; mi < 2; mi++)
#pragma unroll
                    for (int ni = 0; ni < 4; ni++) MMA_BF16(acc[mi][ni], a[mi], b[ni]);
            }
        }

        // scatter acc -> pre-tile [128][64], stride 65
        const int lr = lane >> 2, lc = lane & 3;
#pragma unroll
        for (int mi = 0; mi < 2; mi++)
#pragma unroll
            for (int ni = 0; ni < 4; ni++) {
                int r = wm * 32 + mi * 16 + lr;
                int cc = wn * 32 + ni * 8 + 2 * lc;
                pre[r * 65 + cc]           = acc[mi][ni][0];
                pre[r * 65 + cc + 1]       = acc[mi][ni][1];
                pre[(r + 8) * 65 + cc]     = acc[mi][ni][2];
                pre[(r + 8) * 65 + cc + 1] = acc[mi][ni][3];
            }
        __syncthreads();

        // fused LSTM elementwise: 8 (b,j) pairs per thread (gx bf16 from smem)
#pragma unroll
        for (int s = 0; s < 8; s++) {
            int p = s * 256 + tid;
            int r = p >> 4, jj = p & 15;
            int b = m0 + r;
            const __nv_bfloat162* g2 = reinterpret_cast<const __nv_bfloat162*>(
                smem + GX_OFF + r * GX_STRIDE_B + 8 * jj);
            float2 ga = __bfloat1622float2(g2[0]);
            float2 gb = __bfloat1622float2(g2[1]);
            float p0 = pre[r * 65 + 4 * jj + 0] + ga.x;
            float p1 = pre[r * 65 + 4 * jj + 1] + ga.y;
            float p2 = pre[r * 65 + 4 * jj + 2] + gb.x;
            float p3 = pre[r * 65 + 4 * jj + 3] + gb.y;
            float ig = sigm(p0);
            float fg = sigm(p1);
            float gg = tanhff(p2);
            float og = sigm(p3);
            float cn = fg * creg[s] + ig * gg;
            creg[s] = cn;
            hout[b * HID + (n0 >> 2) + jj] = __float2bfloat16_rn(og * tanhff(cn));
        }

        // ---- per-m-group grid barrier: bar.sync -> release-add -> acquire poll ----
        __syncthreads();                    // all h stores issued; gxs reads done
        if (t + 1 < SEQT) prefetch_gx(t + 1);   // h-independent; overlaps the wait
        CP_COMMIT();
        if (tid == 0) {
            unsigned target = (unsigned)(t + 1) * 64u;
            asm volatile("red.release.gpu.global.add.u32 [%0], %1;"
                         :: "l"(&g_barg[grp]), "r"(1u) : "memory");
            unsigned v;
            do {
                asm volatile("ld.acquire.gpu.global.u32 %0, [%1];"
                             : "=r"(v) : "l"(&g_barg[grp]) : "memory");
            } while (v < target);
        }
        __syncthreads();
    }

    // ======== fused final FC + log_softmax (after t=127 group barrier) ========
    // Each CTA handles 2 batch rows of its own m-group: b = m0 + 2*bx + {0,1}.
    {
        const __nv_bfloat16* __restrict__ hf = g_h[0];   // t=127 wrote buffer 0
        float* hrow = (float*)(smem + A_OFF);            // 2 x 1024 f32 = 8KB
        float* lg   = (float*)(smem + A_OFF + 8192);     // 2 x 32 logits
        const int bx = blockIdx.x;
#pragma unroll
        for (int rr = 0; rr < 2; rr++) {
            int b = m0 + 2 * bx + rr;
            for (int i = tid; i < HID; i += 256)
                hrow[rr * 1024 + i] = __bfloat162float(hf[(size_t)b * HID + i]);
        }
        __syncthreads();

        // 8 warps x 4 outputs = 32 outputs, each for both rows
#pragma unroll
        for (int rr = 0; rr < 2; rr++) {
#pragma unroll
            for (int oo = 0; oo < 4; oo++) {
                int o = wid * 4 + oo;
                const float* w = wfc + (size_t)o * HID;
                float s = 0.f;
                for (int k = lane; k < HID; k += 32) s += hrow[rr * 1024 + k] * w[k];
#pragma unroll
                for (int off = 16; off; off >>= 1) s += __shfl_xor_sync(0xffffffffu, s, off);
                if (lane == 0) lg[rr * 32 + o] = s;
            }
        }
        __syncthreads();

        if (tid < 64) {                     // warp 0 -> row 0, warp 1 -> row 1
            int rr = tid >> 5, oi = tid & 31;
            float l = lg[rr * 32 + oi];
            float m = l;
#pragma unroll
            for (int off = 16; off; off >>= 1) m = fmaxf(m, __shfl_xor_sync(0xffffffffu, m, off));
            float e = expf(l - m);
            float se = e;
#pragma unroll
            for (int off = 16; off; off >>= 1) se += __shfl_xor_sync(0xffffffffu, se, off);
            out[(m0 + 2 * bx + rr) * NOUT + oi] = l - m - logf(se);
        }
    }
}

// ---------------- launch ----------------
extern "C" void kernel_launch(void* const* d_in, const int* in_sizes, int n_in,
                              void* d_out, int out_size) {
    const float* x    = (const float*)d_in[0];
    const float* w_ii = (const float*)d_in[1];
    const float* w_hi = (const float*)d_in[2];
    const float* b_ii = (const float*)d_in[3];
    const float* b_hi = (const float*)d_in[4];
    const float* w_if = (const float*)d_in[5];
    const float* w_hf = (const float*)d_in[6];
    const float* b_if = (const float*)d_in[7];
    const float* b_hf = (const float*)d_in[8];
    const float* w_io = (const float*)d_in[9];
    const float* w_ho = (const float*)d_in[10];
    const float* b_io = (const float*)d_in[11];
    const float* b_ho = (const float*)d_in[12];
    const float* w_ic = (const float*)d_in[13];
    const float* w_hc = (const float*)d_in[14];
    const float* b_ic = (const float*)d_in[15];
    const float* b_hc = (const float*)d_in[16];
    const float* w_fc = (const float*)d_in[17];

    cudaFuncSetAttribute(k_gemm_x, cudaFuncAttributeMaxDynamicSharedMemorySize, X_SMEM);
    cudaFuncSetAttribute(k_steps,  cudaFuncAttributeMaxDynamicSharedMemorySize, S_SMEM);

    k_prep0<<<2048, 256>>>(x, w_ii, w_if, w_ic, w_io, w_hi, w_hf, w_hc, w_ho);
    k_prep1<<<1024, 256>>>(b_ii, b_hi, b_if, b_hf, b_ic, b_hc, b_io, b_ho);

    k_gemm_x<<<dim3(32, 256), 256, X_SMEM>>>();

    k_steps<<<dim3(64, 2), 256, S_SMEM>>>(w_fc, (float*)d_out);
}

// round 16
// speedup vs baseline: 1.0613x; 1.0076x over previous
#include <cuda_runtime.h>
#include <cuda_bf16.h>
#include <cstdint>
#include <math.h>

#define BATCH 256
#define SEQT  128
#define INP   512
#define HID   1024
#define NOUT  32
#define NG    4096   // 4*HID, interleaved gates: n = 4*j + g (0=i,1=f,2=cell,3=o)

// ---------------- scratch (device globals; no cudaMalloc allowed) ----------------
__device__ __nv_bfloat16 g_gx[(size_t)BATCH * SEQT * NG];    // input-proj preacts + bias (bf16)
__device__ __nv_bfloat16 g_xr[(size_t)BATCH * SEQT * INP];   // bf16 inputs
__device__ __nv_bfloat16 g_wi[(size_t)NG * INP];             // packed bf16 input weights
__device__ __nv_bfloat16 g_wh[(size_t)NG * HID];             // packed bf16 hidden weights
__device__ float         g_bias[NG];
__device__ __nv_bfloat16 g_h[2][BATCH * HID];                // double-buffered hidden state
__device__ unsigned      g_barg[2];                          // per-m-group barrier counters

// ---------------- helpers ----------------
__device__ __forceinline__ uint32_t smem_u32(const void* p) {
    return (uint32_t)__cvta_generic_to_shared(p);
}
__device__ __forceinline__ void cp16s(uint32_t dst, const void* src) {
    asm volatile("cp.async.cg.shared.global [%0], [%1], 16;" :: "r"(dst), "l"(src));
}
#define CP_COMMIT() asm volatile("cp.async.commit_group;" ::: "memory")
#define CP_WAIT0()  asm volatile("cp.async.wait_group 0;" ::: "memory")
#define CP_WAIT1()  asm volatile("cp.async.wait_group 1;" ::: "memory")

// 64B-row smem layout (BK=32 bf16), 16B chunk swizzle (R4-proven).
__device__ __forceinline__ uint32_t sw(int row, int c) {
    return (uint32_t)(row * 64 + ((c ^ ((row >> 1) & 3)) << 4));
}
// Persistent Wh smem: 2KB rows (K=1024 bf16), per-row chunk swizzle.
__device__ __forceinline__ uint32_t whsw(int row, int c) {
    return (uint32_t)(row * 2048 + ((c ^ (row & 7)) << 4));
}

__device__ __forceinline__ void ldsm4(uint32_t& r0, uint32_t& r1, uint32_t& r2, uint32_t& r3,
                                      uint32_t addr) {
    asm volatile("ldmatrix.sync.aligned.m8n8.x4.shared.b16 {%0,%1,%2,%3}, [%4];"
                 : "=r"(r0), "=r"(r1), "=r"(r2), "=r"(r3) : "r"(addr));
}

#define MMA_BF16(acc, a, b)                                                          \
    asm volatile(                                                                    \
        "mma.sync.aligned.m16n8k16.row.col.f32.bf16.bf16.f32 "                       \
        "{%0,%1,%2,%3},{%4,%5,%6,%7},{%8,%9},{%0,%1,%2,%3};"                         \
        : "+f"(acc[0]), "+f"(acc[1]), "+f"(acc[2]), "+f"(acc[3])                     \
        : "r"(a[0]), "r"(a[1]), "r"(a[2]), "r"(a[3]), "r"(b[0]), "r"(b[1]))

__device__ __forceinline__ float sigm(float x)   { return 1.f / (1.f + __expf(-x)); }
__device__ __forceinline__ float tanhff(float x) { return 1.f - 2.f / (__expf(2.f * x) + 1.f); }

// pack 4 floats -> 4 bf16 (8 bytes); per-element rounding identical to scalar path
__device__ __forceinline__ uint2 bf4(float4 v) {
    __nv_bfloat162 lo = __float22bfloat162_rn(make_float2(v.x, v.y));
    __nv_bfloat162 hi = __float22bfloat162_rn(make_float2(v.z, v.w));
    uint2 r;
    r.x = *reinterpret_cast<uint32_t*>(&lo);
    r.y = *reinterpret_cast<uint32_t*>(&hi);
    return r;
}

// ---------------- prep (2 kernels so k_steps is the 4th launch for ncu) ----------------
// Vectorized (float4 loads, 8B stores) at FULL grid sizes (R14 confound removed).
__global__ void k_prep0(const float* __restrict__ x,
                        const float* __restrict__ wii, const float* __restrict__ wif,
                        const float* __restrict__ wic, const float* __restrict__ wio,
                        const float* __restrict__ whi, const float* __restrict__ whf,
                        const float* __restrict__ whc, const float* __restrict__ who) {
    const size_t stride = (size_t)gridDim.x * blockDim.x;
    const size_t t0 = (size_t)blockIdx.x * blockDim.x + threadIdx.x;

    for (size_t i = t0; i < (size_t)BATCH * SEQT * INP / 4; i += stride) {
        float4 v = reinterpret_cast<const float4*>(x)[i];
        reinterpret_cast<uint2*>(g_xr)[i] = bf4(v);
    }
    for (size_t i = t0; i < (size_t)NG * INP / 4; i += stride) {
        size_t e = i * 4;
        int n = (int)(e / INP), k = (int)(e % INP);
        int g = n & 3, j = n >> 2;
        const float* w = (g == 0) ? wii : (g == 1) ? wif : (g == 2) ? wic : wio;
        float4 v = *reinterpret_cast<const float4*>(&w[(size_t)j * INP + k]);
        reinterpret_cast<uint2*>(g_wi)[i] = bf4(v);
    }
    for (size_t i = t0; i < (size_t)NG * HID / 4; i += stride) {
        size_t e = i * 4;
        int n = (int)(e / HID), k = (int)(e % HID);
        int g = n & 3, j = n >> 2;
        const float* w = (g == 0) ? whi : (g == 1) ? whf : (g == 2) ? whc : who;
        float4 v = *reinterpret_cast<const float4*>(&w[(size_t)j * HID + k]);
        reinterpret_cast<uint2*>(g_wh)[i] = bf4(v);
    }
}

__global__ void k_prep1(const float* bii, const float* bhi, const float* bif, const float* bhf,
                        const float* bic, const float* bhc, const float* bio, const float* bho) {
    int i = blockIdx.x * blockDim.x + threadIdx.x;
    if (i < BATCH * HID / 4)
        reinterpret_cast<uint2*>(g_h[0])[i] = make_uint2(0u, 0u);
    if (i < NG) {
        int g = i & 3, j = i >> 2;
        float v;
        if (g == 0)      v = bii[j] + bhi[j];
        else if (g == 1) v = bif[j] + bhf[j];
        else if (g == 2) v = bic[j] + bhc[j];
        else             v = bio[j] + bho[j];
        g_bias[i] = v;
    }
    if (i < 2) g_barg[i] = 0u;
}

// ============================================================================
// Input GEMM (R12, unchanged): g_gx = bf16(Xr @ Wi^T + bias)
// CTA tile 128 x 128, K=512, BK=32, 3-stage cp.async, 1 barrier/slab.
// 8 warps as 4m x 2n; warp tile 32x64. Grid (32 n, 256 m). 48KB smem.
// ============================================================================
static const int X_SMEM = 49152;

__global__ __launch_bounds__(256, 1) void k_gemm_x() {
    extern __shared__ char smem[];
    const uint32_t sb = smem_u32(smem);
    const int tid = threadIdx.x, lane = tid & 31, wid = tid >> 5;
    const int wm = wid & 3, wn = wid >> 2;
    const int n0 = blockIdx.x * 128, m0 = blockIdx.y * 128;

    float acc[2][8][4];
#pragma unroll
    for (int mi = 0; mi < 2; mi++)
#pragma unroll
        for (int ni = 0; ni < 8; ni++)
#pragma unroll
            for (int q = 0; q < 4; q++) acc[mi][ni][q] = 0.f;

    auto load_slab = [&](int s) {
        const uint32_t ab = sb + (uint32_t)(s % 3) * 16384u;
        const int k0 = s * 32;
#pragma unroll
        for (int i = 0; i < 2; i++) {
            int q = tid + i * 256, row = q >> 2, c = q & 3;
            cp16s(ab + sw(row, c), g_xr + (size_t)(m0 + row) * INP + k0 + c * 8);
        }
#pragma unroll
        for (int i = 0; i < 2; i++) {
            int q = tid + i * 256, row = q >> 2, c = q & 3;
            cp16s(ab + 8192u + sw(row, c), g_wi + (size_t)(n0 + row) * INP + k0 + c * 8);
        }
    };

    const int KT = INP / 32;
    load_slab(0); CP_COMMIT();
    load_slab(1); CP_COMMIT();
    for (int kt = 0; kt < KT; kt++) {
        if (kt + 1 < KT) CP_WAIT1(); else CP_WAIT0();
        __syncthreads();
        if (kt + 2 < KT) { load_slab(kt + 2); CP_COMMIT(); }
        const uint32_t ab = sb + (uint32_t)(kt % 3) * 16384u;
        const uint32_t bb = ab + 8192u;
#pragma unroll
        for (int ks = 0; ks < 2; ks++) {
            uint32_t a[2][4];
#pragma unroll
            for (int mi = 0; mi < 2; mi++) {
                int row = wm * 32 + mi * 16 + (lane & 15);
                int c = 2 * ks + (lane >> 4);
                ldsm4(a[mi][0], a[mi][1], a[mi][2], a[mi][3], ab + sw(row, c));
            }
            uint32_t b[8][2];
#pragma unroll
            for (int nt = 0; nt < 4; nt++) {
                int row = wn * 64 + nt * 16 + ((lane >> 4) << 3) + (lane & 7);
                int c = 2 * ks + ((lane >> 3) & 1);
                ldsm4(b[2 * nt][0], b[2 * nt][1], b[2 * nt + 1][0], b[2 * nt + 1][1],
                      bb + sw(row, c));
            }
#pragma unroll
            for (int mi = 0; mi < 2; mi++)
#pragma unroll
                for (int ni = 0; ni < 8; ni++) MMA_BF16(acc[mi][ni], a[mi], b[ni]);
        }
    }

    const int lr = lane >> 2, lc = lane & 3;
#pragma unroll
    for (int mi = 0; mi < 2; mi++)
#pragma unroll
        for (int ni = 0; ni < 8; ni++) {
            int r = wm * 32 + mi * 16 + lr;
            int cc = wn * 64 + ni * 8 + 2 * lc;
            int n = n0 + cc;
            float b0 = g_bias[n], b1 = g_bias[n + 1];
            __nv_bfloat162 v0 = __float22bfloat162_rn(
                make_float2(acc[mi][ni][0] + b0, acc[mi][ni][1] + b1));
            __nv_bfloat162 v1 = __float22bfloat162_rn(
                make_float2(acc[mi][ni][2] + b0, acc[mi][ni][3] + b1));
            *reinterpret_cast<__nv_bfloat162*>(&g_gx[(size_t)(m0 + r) * NG + n])     = v0;
            *reinterpret_cast<__nv_bfloat162*>(&g_gx[(size_t)(m0 + r + 8) * NG + n]) = v1;
        }
}

// ============================================================================
// Persistent step kernel (R13, unchanged): R12 mainloop/epilogue, release/
// acquire grid barrier, gx[t+1] prefetch overlapping the barrier wait.
// Smem: [0,128K) Wh | [128K,+24K) A | [155648,+18432) gx | [174080,+33280) pre.
// ============================================================================
static const int A_OFF   = 131072;
static const int GX_OFF  = 131072 + 3 * 8192;            // 155648
static const int GX_STRIDE_B = 144;                      // 64 bf16 = 128B + 16B pad
static const int PRE_OFF = GX_OFF + 128 * GX_STRIDE_B;   // 174080
static const int S_SMEM  = PRE_OFF + 33280;              // 207360

__global__ __launch_bounds__(256, 1) void k_steps(const float* __restrict__ wfc,
                                                  float* __restrict__ out) {
    extern __shared__ char smem[];
    const uint32_t sb = smem_u32(smem);
    const int tid = threadIdx.x, lane = tid & 31, wid = tid >> 5;
    const int wm = wid & 3, wn = wid >> 2;
    const int n0 = blockIdx.x * 64, m0 = blockIdx.y * 128;
    const int grp = blockIdx.y;

    // ---- load Wh slice (64 rows x 1024 bf16 = 128KB) into persistent smem ----
#pragma unroll
    for (int i = 0; i < 32; i++) {
        int idx = tid + i * 256;            // 8192 16B-chunks
        int row = idx >> 7, c = idx & 127;
        cp16s(sb + whsw(row, c), g_wh + (size_t)(n0 + row) * HID + c * 8);
    }
    CP_COMMIT();

    auto prefetch_gx = [&](int t) {
#pragma unroll
        for (int i = 0; i < 4; i++) {       // 1024 16B-chunks, 4/thread
            int idx = tid + i * 256;
            int row = idx >> 3, c = idx & 7;
            cp16s(sb + GX_OFF + (uint32_t)(row * GX_STRIDE_B + c * 16),
                  &g_gx[((size_t)(m0 + row) * SEQT + t) * NG + n0 + c * 8]);
        }
    };

    // gx[0] prefetch (own group; completes under the first mainloop wait)
    prefetch_gx(0); CP_COMMIT();

    float creg[8];
#pragma unroll
    for (int q = 0; q < 8; q++) creg[q] = 0.f;

    float* pre = (float*)(smem + PRE_OFF);
    const int KT = HID / 32;   // 32

    for (int t = 0; t < SEQT; t++) {
        const __nv_bfloat16* __restrict__ hin = g_h[t & 1];
        __nv_bfloat16* __restrict__ hout = g_h[(t + 1) & 1];

        float acc[2][4][4];
#pragma unroll
        for (int mi = 0; mi < 2; mi++)
#pragma unroll
            for (int ni = 0; ni < 4; ni++)
#pragma unroll
                for (int q = 0; q < 4; q++) acc[mi][ni][q] = 0.f;

        auto load_slab = [&](int s) {
            const uint32_t ab = sb + A_OFF + (uint32_t)(s % 3) * 8192u;
            const int k0 = s * 32;
#pragma unroll
            for (int i = 0; i < 2; i++) {   // A: 128 rows x 4 chunks
                int q = tid + i * 256, row = q >> 2, c = q & 3;
                cp16s(ab + sw(row, c), hin + (size_t)(m0 + row) * HID + k0 + c * 8);
            }
        };

        load_slab(0); CP_COMMIT();
        load_slab(1); CP_COMMIT();

        for (int kt = 0; kt < KT; kt++) {
            if (kt + 1 < KT) CP_WAIT1(); else CP_WAIT0();
            __syncthreads();
            if (kt + 2 < KT) { load_slab(kt + 2); CP_COMMIT(); }
            const uint32_t ab = sb + A_OFF + (uint32_t)(kt % 3) * 8192u;
#pragma unroll
            for (int ks = 0; ks < 2; ks++) {
                uint32_t a[2][4];
#pragma unroll
                for (int mi = 0; mi < 2; mi++) {
                    int row = wm * 32 + mi * 16 + (lane & 15);
                    int c = 2 * ks + (lane >> 4);
                    ldsm4(a[mi][0], a[mi][1], a[mi][2], a[mi][3], ab + sw(row, c));
                }
                uint32_t b[4][2];
#pragma unroll
                for (int nt = 0; nt < 2; nt++) {
                    int row = wn * 32 + nt * 16 + ((lane >> 4) << 3) + (lane & 7);
                    int gc = kt * 4 + 2 * ks + ((lane >> 3) & 1);
                    ldsm4(b[2 * nt][0], b[2 * nt][1], b[2 * nt + 1][0], b[2 * nt + 1][1],
                          sb + whsw(row, gc));
                }
#pragma unroll
                for (int mi = 0; mi < 2; mi++)
#pragma unroll
                    for (int ni = 0; ni < 4; ni++) MMA_BF16(acc[mi][ni], a[mi], b[ni]);
            }
        }

        // scatter acc -> pre-tile [128][64], stride 65
        const int lr = lane >> 2, lc = lane & 3;
#pragma unroll
        for (int mi = 0; mi < 2; mi++)
#pragma unroll
            for (int ni = 0; ni < 4; ni++) {
                int r = wm * 32 + mi * 16 + lr;
                int cc = wn * 32 + ni * 8 + 2 * lc;
                pre[r * 65 + cc]           = acc[mi][ni][0];
                pre[r * 65 + cc + 1]       = acc[mi][ni][1];
                pre[(r + 8) * 65 + cc]     = acc[mi][ni][2];
                pre[(r + 8) * 65 + cc + 1] = acc[mi][ni][3];
            }
        __syncthreads();

        // fused LSTM elementwise: 8 (b,j) pairs per thread (gx bf16 from smem)
#pragma unroll
        for (int s = 0; s < 8; s++) {
            int p = s * 256 + tid;
            int r = p >> 4, jj = p & 15;
            int b = m0 + r;
            const __nv_bfloat162* g2 = reinterpret_cast<const __nv_bfloat162*>(
                smem + GX_OFF + r * GX_STRIDE_B + 8 * jj);
            float2 ga = __bfloat1622float2(g2[0]);
            float2 gb = __bfloat1622float2(g2[1]);
            float p0 = pre[r * 65 + 4 * jj + 0] + ga.x;
            float p1 = pre[r * 65 + 4 * jj + 1] + ga.y;
            float p2 = pre[r * 65 + 4 * jj + 2] + gb.x;
            float p3 = pre[r * 65 + 4 * jj + 3] + gb.y;
            float ig = sigm(p0);
            float fg = sigm(p1);
            float gg = tanhff(p2);
            float og = sigm(p3);
            float cn = fg * creg[s] + ig * gg;
            creg[s] = cn;
            hout[b * HID + (n0 >> 2) + jj] = __float2bfloat16_rn(og * tanhff(cn));
        }

        // ---- per-m-group grid barrier: bar.sync -> release-add -> acquire poll ----
        __syncthreads();                    // all h stores issued; gxs reads done
        if (t + 1 < SEQT) prefetch_gx(t + 1);   // h-independent; overlaps the wait
        CP_COMMIT();
        if (tid == 0) {
            unsigned target = (unsigned)(t + 1) * 64u;
            asm volatile("red.release.gpu.global.add.u32 [%0], %1;"
                         :: "l"(&g_barg[grp]), "r"(1u) : "memory");
            unsigned v;
            do {
                asm volatile("ld.acquire.gpu.global.u32 %0, [%1];"
                             : "=r"(v) : "l"(&g_barg[grp]) : "memory");
            } while (v < target);
        }
        __syncthreads();
    }

    // ======== fused final FC + log_softmax (after t=127 group barrier) ========
    // Each CTA handles 2 batch rows of its own m-group: b = m0 + 2*bx + {0,1}.
    {
        const __nv_bfloat16* __restrict__ hf = g_h[0];   // t=127 wrote buffer 0
        float* hrow = (float*)(smem + A_OFF);            // 2 x 1024 f32 = 8KB
        float* lg   = (float*)(smem + A_OFF + 8192);     // 2 x 32 logits
        const int bx = blockIdx.x;
#pragma unroll
        for (int rr = 0; rr < 2; rr++) {
            int b = m0 + 2 * bx + rr;
            for (int i = tid; i < HID; i += 256)
                hrow[rr * 1024 + i] = __bfloat162float(hf[(size_t)b * HID + i]);
        }
        __syncthreads();

        // 8 warps x 4 outputs = 32 outputs, each for both rows
#pragma unroll
        for (int rr = 0; rr < 2; rr++) {
#pragma unroll
            for (int oo = 0; oo < 4; oo++) {
                int o = wid * 4 + oo;
                const float* w = wfc + (size_t)o * HID;
                float s = 0.f;
                for (int k = lane; k < HID; k += 32) s += hrow[rr * 1024 + k] * w[k];
#pragma unroll
                for (int off = 16; off; off >>= 1) s += __shfl_xor_sync(0xffffffffu, s, off);
                if (lane == 0) lg[rr * 32 + o] = s;
            }
        }
        __syncthreads();

        if (tid < 64) {                     // warp 0 -> row 0, warp 1 -> row 1
            int rr = tid >> 5, oi = tid & 31;
            float l = lg[rr * 32 + oi];
            float m = l;
#pragma unroll
            for (int off = 16; off; off >>= 1) m = fmaxf(m, __shfl_xor_sync(0xffffffffu, m, off));
            float e = expf(l - m);
            float se = e;
#pragma unroll
            for (int off = 16; off; off >>= 1) se += __shfl_xor_sync(0xffffffffu, se, off);
            out[(m0 + 2 * bx + rr) * NOUT + oi] = l - m - logf(se);
        }
    }
}

// ---------------- launch ----------------
extern "C" void kernel_launch(void* const* d_in, const int* in_sizes, int n_in,
                              void* d_out, int out_size) {
    const float* x    = (const float*)d_in[0];
    const float* w_ii = (const float*)d_in[1];
    const float* w_hi = (const float*)d_in[2];
    const float* b_ii = (const float*)d_in[3];
    const float* b_hi = (const float*)d_in[4];
    const float* w_if = (const float*)d_in[5];
    const float* w_hf = (const float*)d_in[6];
    const float* b_if = (const float*)d_in[7];
    const float* b_hf = (const float*)d_in[8];
    const float* w_io = (const float*)d_in[9];
    const float* w_ho = (const float*)d_in[10];
    const float* b_io = (const float*)d_in[11];
    const float* b_ho = (const float*)d_in[12];
    const float* w_ic = (const float*)d_in[13];
    const float* w_hc = (const float*)d_in[14];
    const float* b_ic = (const float*)d_in[15];
    const float* b_hc = (const float*)d_in[16];
    const float* w_fc = (const float*)d_in[17];

    cudaFuncSetAttribute(k_gemm_x, cudaFuncAttributeMaxDynamicSharedMemorySize, X_SMEM);
    cudaFuncSetAttribute(k_steps,  cudaFuncAttributeMaxDynamicSharedMemorySize, S_SMEM);

    k_prep0<<<2048, 256>>>(x, w_ii, w_if, w_ic, w_io, w_hi, w_hf, w_hc, w_ho);
    k_prep1<<<1024, 256>>>(b_ii, b_hi, b_if, b_hf, b_ic, b_hc, b_io, b_ho);

    k_gemm_x<<<dim3(32, 256), 256, X_SMEM>>>();

    k_steps<<<dim3(64, 2), 256, S_SMEM>>>(w_fc, (float*)d_out);
}

// round 17
// speedup vs baseline: 1.0631x; 1.0017x over previous
#include <cuda_runtime.h>
#include <cuda_bf16.h>
#include <cstdint>
#include <math.h>

#define BATCH 256
#define SEQT  128
#define INP   512
#define HID   1024
#define NOUT  32
#define NG    4096   // 4*HID, interleaved gates: n = 4*j + g (0=i,1=f,2=cell,3=o)

// ---------------- scratch (device globals; no cudaMalloc allowed) ----------------
__device__ __nv_bfloat16 g_gx[(size_t)BATCH * SEQT * NG];    // input-proj preacts + bias (bf16)
__device__ __nv_bfloat16 g_xr[(size_t)BATCH * SEQT * INP];   // bf16 inputs
__device__ __nv_bfloat16 g_wi[(size_t)NG * INP];             // packed bf16 input weights
__device__ __nv_bfloat16 g_wh[(size_t)NG * HID];             // packed bf16 hidden weights
__device__ float         g_bias[NG];
__device__ __nv_bfloat16 g_h[2][BATCH * HID];                // double-buffered hidden state
__device__ unsigned      g_barg[2];                          // per-m-group barrier counters

// ---------------- helpers ----------------
__device__ __forceinline__ uint32_t smem_u32(const void* p) {
    return (uint32_t)__cvta_generic_to_shared(p);
}
__device__ __forceinline__ void cp16s(uint32_t dst, const void* src) {
    asm volatile("cp.async.cg.shared.global [%0], [%1], 16;" :: "r"(dst), "l"(src));
}
#define CP_COMMIT() asm volatile("cp.async.commit_group;" ::: "memory")
#define CP_WAIT0()  asm volatile("cp.async.wait_group 0;" ::: "memory")
#define CP_WAIT1()  asm volatile("cp.async.wait_group 1;" ::: "memory")

// 64B-row smem layout (BK=32 bf16), 16B chunk swizzle (R4-proven).
__device__ __forceinline__ uint32_t sw(int row, int c) {
    return (uint32_t)(row * 64 + ((c ^ ((row >> 1) & 3)) << 4));
}
// Persistent Wh smem: 2KB rows (K=1024 bf16), per-row chunk swizzle.
__device__ __forceinline__ uint32_t whsw(int row, int c) {
    return (uint32_t)(row * 2048 + ((c ^ (row & 7)) << 4));
}

__device__ __forceinline__ void ldsm4(uint32_t& r0, uint32_t& r1, uint32_t& r2, uint32_t& r3,
                                      uint32_t addr) {
    asm volatile("ldmatrix.sync.aligned.m8n8.x4.shared.b16 {%0,%1,%2,%3}, [%4];"
                 : "=r"(r0), "=r"(r1), "=r"(r2), "=r"(r3) : "r"(addr));
}

#define MMA_BF16(acc, a, b)                                                          \
    asm volatile(                                                                    \
        "mma.sync.aligned.m16n8k16.row.col.f32.bf16.bf16.f32 "                       \
        "{%0,%1,%2,%3},{%4,%5,%6,%7},{%8,%9},{%0,%1,%2,%3};"                         \
        : "+f"(acc[0]), "+f"(acc[1]), "+f"(acc[2]), "+f"(acc[3])                     \
        : "r"(a[0]), "r"(a[1]), "r"(a[2]), "r"(a[3]), "r"(b[0]), "r"(b[1]))

__device__ __forceinline__ float sigm(float x)   { return 1.f / (1.f + __expf(-x)); }
__device__ __forceinline__ float tanhff(float x) { return 1.f - 2.f / (__expf(2.f * x) + 1.f); }

// pack 4 floats -> 4 bf16 (8 bytes); per-element rounding identical to scalar path
__device__ __forceinline__ uint2 bf4(float4 v) {
    __nv_bfloat162 lo = __float22bfloat162_rn(make_float2(v.x, v.y));
    __nv_bfloat162 hi = __float22bfloat162_rn(make_float2(v.z, v.w));
    uint2 r;
    r.x = *reinterpret_cast<uint32_t*>(&lo);
    r.y = *reinterpret_cast<uint32_t*>(&hi);
    return r;
}

// ---------------- prep: single kernel (x/wi/wh convert + bias + h-zero + bar init) ----------------
__global__ void k_prep(const float* __restrict__ x,
                       const float* __restrict__ wii, const float* __restrict__ wif,
                       const float* __restrict__ wic, const float* __restrict__ wio,
                       const float* __restrict__ whi, const float* __restrict__ whf,
                       const float* __restrict__ whc, const float* __restrict__ who,
                       const float* __restrict__ bii, const float* __restrict__ bhi,
                       const float* __restrict__ bif, const float* __restrict__ bhf,
                       const float* __restrict__ bic, const float* __restrict__ bhc,
                       const float* __restrict__ bio, const float* __restrict__ bho) {
    const size_t stride = (size_t)gridDim.x * blockDim.x;
    const size_t t0 = (size_t)blockIdx.x * blockDim.x + threadIdx.x;

    for (size_t i = t0; i < (size_t)BATCH * SEQT * INP / 4; i += stride) {
        float4 v = reinterpret_cast<const float4*>(x)[i];
        reinterpret_cast<uint2*>(g_xr)[i] = bf4(v);
    }
    for (size_t i = t0; i < (size_t)NG * INP / 4; i += stride) {
        size_t e = i * 4;
        int n = (int)(e / INP), k = (int)(e % INP);
        int g = n & 3, j = n >> 2;
        const float* w = (g == 0) ? wii : (g == 1) ? wif : (g == 2) ? wic : wio;
        float4 v = *reinterpret_cast<const float4*>(&w[(size_t)j * INP + k]);
        reinterpret_cast<uint2*>(g_wi)[i] = bf4(v);
    }
    for (size_t i = t0; i < (size_t)NG * HID / 4; i += stride) {
        size_t e = i * 4;
        int n = (int)(e / HID), k = (int)(e % HID);
        int g = n & 3, j = n >> 2;
        const float* w = (g == 0) ? whi : (g == 1) ? whf : (g == 2) ? whc : who;
        float4 v = *reinterpret_cast<const float4*>(&w[(size_t)j * HID + k]);
        reinterpret_cast<uint2*>(g_wh)[i] = bf4(v);
    }
    // bias, h-zero, barrier init (small; only low thread ids do work)
    const size_t gt = t0;
    if (gt < NG) {
        int g = (int)gt & 3, j = (int)gt >> 2;
        float v;
        if (g == 0)      v = bii[j] + bhi[j];
        else if (g == 1) v = bif[j] + bhf[j];
        else if (g == 2) v = bic[j] + bhc[j];
        else             v = bio[j] + bho[j];
        g_bias[gt] = v;
    }
    if (gt < BATCH * HID / 4)
        reinterpret_cast<uint2*>(g_h[0])[gt] = make_uint2(0u, 0u);
    if (gt < 2) g_barg[gt] = 0u;
}

// ============================================================================
// Input GEMM (R12, unchanged): g_gx = bf16(Xr @ Wi^T + bias)
// CTA tile 128 x 128, K=512, BK=32, 3-stage cp.async, 1 barrier/slab.
// 8 warps as 4m x 2n; warp tile 32x64. Grid (32 n, 256 m). 48KB smem.
// ============================================================================
static const int X_SMEM = 49152;

__global__ __launch_bounds__(256, 1) void k_gemm_x() {
    extern __shared__ char smem[];
    const uint32_t sb = smem_u32(smem);
    const int tid = threadIdx.x, lane = tid & 31, wid = tid >> 5;
    const int wm = wid & 3, wn = wid >> 2;
    const int n0 = blockIdx.x * 128, m0 = blockIdx.y * 128;

    float acc[2][8][4];
#pragma unroll
    for (int mi = 0; mi < 2; mi++)
#pragma unroll
        for (int ni = 0; ni < 8; ni++)
#pragma unroll
            for (int q = 0; q < 4; q++) acc[mi][ni][q] = 0.f;

    auto load_slab = [&](int s) {
        const uint32_t ab = sb + (uint32_t)(s % 3) * 16384u;
        const int k0 = s * 32;
#pragma unroll
        for (int i = 0; i < 2; i++) {
            int q = tid + i * 256, row = q >> 2, c = q & 3;
            cp16s(ab + sw(row, c), g_xr + (size_t)(m0 + row) * INP + k0 + c * 8);
        }
#pragma unroll
        for (int i = 0; i < 2; i++) {
            int q = tid + i * 256, row = q >> 2, c = q & 3;
            cp16s(ab + 8192u + sw(row, c), g_wi + (size_t)(n0 + row) * INP + k0 + c * 8);
        }
    };

    const int KT = INP / 32;
    load_slab(0); CP_COMMIT();
    load_slab(1); CP_COMMIT();
    for (int kt = 0; kt < KT; kt++) {
        if (kt + 1 < KT) CP_WAIT1(); else CP_WAIT0();
        __syncthreads();
        if (kt + 2 < KT) { load_slab(kt + 2); CP_COMMIT(); }
        const uint32_t ab = sb + (uint32_t)(kt % 3) * 16384u;
        const uint32_t bb = ab + 8192u;
#pragma unroll
        for (int ks = 0; ks < 2; ks++) {
            uint32_t a[2][4];
#pragma unroll
            for (int mi = 0; mi < 2; mi++) {
                int row = wm * 32 + mi * 16 + (lane & 15);
                int c = 2 * ks + (lane >> 4);
                ldsm4(a[mi][0], a[mi][1], a[mi][2], a[mi][3], ab + sw(row, c));
            }
            uint32_t b[8][2];
#pragma unroll
            for (int nt = 0; nt < 4; nt++) {
                int row = wn * 64 + nt * 16 + ((lane >> 4) << 3) + (lane & 7);
                int c = 2 * ks + ((lane >> 3) & 1);
                ldsm4(b[2 * nt][0], b[2 * nt][1], b[2 * nt + 1][0], b[2 * nt + 1][1],
                      bb + sw(row, c));
            }
#pragma unroll
            for (int mi = 0; mi < 2; mi++)
#pragma unroll
                for (int ni = 0; ni < 8; ni++) MMA_BF16(acc[mi][ni], a[mi], b[ni]);
        }
    }

    const int lr = lane >> 2, lc = lane & 3;
#pragma unroll
    for (int mi = 0; mi < 2; mi++)
#pragma unroll
        for (int ni = 0; ni < 8; ni++) {
            int r = wm * 32 + mi * 16 + lr;
            int cc = wn * 64 + ni * 8 + 2 * lc;
            int n = n0 + cc;
            float b0 = g_bias[n], b1 = g_bias[n + 1];
            __nv_bfloat162 v0 = __float22bfloat162_rn(
                make_float2(acc[mi][ni][0] + b0, acc[mi][ni][1] + b1));
            __nv_bfloat162 v1 = __float22bfloat162_rn(
                make_float2(acc[mi][ni][2] + b0, acc[mi][ni][3] + b1));
            *reinterpret_cast<__nv_bfloat162*>(&g_gx[(size_t)(m0 + r) * NG + n])     = v0;
            *reinterpret_cast<__nv_bfloat162*>(&g_gx[(size_t)(m0 + r + 8) * NG + n]) = v1;
        }
}

// ============================================================================
// Persistent step kernel (R13, unchanged): R12 mainloop/epilogue, release/
// acquire grid barrier, gx[t+1] prefetch overlapping the barrier wait.
// Smem: [0,128K) Wh | [128K,+24K) A | [155648,+18432) gx | [174080,+33280) pre.
// ============================================================================
static const int A_OFF   = 131072;
static const int GX_OFF  = 131072 + 3 * 8192;            // 155648
static const int GX_STRIDE_B = 144;                      // 64 bf16 = 128B + 16B pad
static const int PRE_OFF = GX_OFF + 128 * GX_STRIDE_B;   // 174080
static const int S_SMEM  = PRE_OFF + 33280;              // 207360

__global__ __launch_bounds__(256, 1) void k_steps(const float* __restrict__ wfc,
                                                  float* __restrict__ out) {
    extern __shared__ char smem[];
    const uint32_t sb = smem_u32(smem);
    const int tid = threadIdx.x, lane = tid & 31, wid = tid >> 5;
    const int wm = wid & 3, wn = wid >> 2;
    const int n0 = blockIdx.x * 64, m0 = blockIdx.y * 128;
    const int grp = blockIdx.y;

    // ---- load Wh slice (64 rows x 1024 bf16 = 128KB) into persistent smem ----
#pragma unroll
    for (int i = 0; i < 32; i++) {
        int idx = tid + i * 256;            // 8192 16B-chunks
        int row = idx >> 7, c = idx & 127;
        cp16s(sb + whsw(row, c), g_wh + (size_t)(n0 + row) * HID + c * 8);
    }
    CP_COMMIT();

    auto prefetch_gx = [&](int t) {
#pragma unroll
        for (int i = 0; i < 4; i++) {       // 1024 16B-chunks, 4/thread
            int idx = tid + i * 256;
            int row = idx >> 3, c = idx & 7;
            cp16s(sb + GX_OFF + (uint32_t)(row * GX_STRIDE_B + c * 16),
                  &g_gx[((size_t)(m0 + row) * SEQT + t) * NG + n0 + c * 8]);
        }
    };

    // gx[0] prefetch (own group; completes under the first mainloop wait)
    prefetch_gx(0); CP_COMMIT();

    float creg[8];
#pragma unroll
    for (int q = 0; q < 8; q++) creg[q] = 0.f;

    float* pre = (float*)(smem + PRE_OFF);
    const int KT = HID / 32;   // 32

    for (int t = 0; t < SEQT; t++) {
        const __nv_bfloat16* __restrict__ hin = g_h[t & 1];
        __nv_bfloat16* __restrict__ hout = g_h[(t + 1) & 1];

        float acc[2][4][4];
#pragma unroll
        for (int mi = 0; mi < 2; mi++)
#pragma unroll
            for (int ni = 0; ni < 4; ni++)
#pragma unroll
                for (int q = 0; q < 4; q++) acc[mi][ni][q] = 0.f;

        auto load_slab = [&](int s) {
            const uint32_t ab = sb + A_OFF + (uint32_t)(s % 3) * 8192u;
            const int k0 = s * 32;
#pragma unroll
            for (int i = 0; i < 2; i++) {   // A: 128 rows x 4 chunks
                int q = tid + i * 256, row = q >> 2, c = q & 3;
                cp16s(ab + sw(row, c), hin + (size_t)(m0 + row) * HID + k0 + c * 8);
            }
        };

        load_slab(0); CP_COMMIT();
        load_slab(1); CP_COMMIT();

        for (int kt = 0; kt < KT; kt++) {
            if (kt + 1 < KT) CP_WAIT1(); else CP_WAIT0();
            __syncthreads();
            if (kt + 2 < KT) { load_slab(kt + 2); CP_COMMIT(); }
            const uint32_t ab = sb + A_OFF + (uint32_t)(kt % 3) * 8192u;
#pragma unroll
            for (int ks = 0; ks < 2; ks++) {
                uint32_t a[2][4];
#pragma unroll
                for (int mi = 0; mi < 2; mi++) {
                    int row = wm * 32 + mi * 16 + (lane & 15);
                    int c = 2 * ks + (lane >> 4);
                    ldsm4(a[mi][0], a[mi][1], a[mi][2], a[mi][3], ab + sw(row, c));
                }
                uint32_t b[4][2];
#pragma unroll
                for (int nt = 0; nt < 2; nt++) {
                    int row = wn * 32 + nt * 16 + ((lane >> 4) << 3) + (lane & 7);
                    int gc = kt * 4 + 2 * ks + ((lane >> 3) & 1);
                    ldsm4(b[2 * nt][0], b[2 * nt][1], b[2 * nt + 1][0], b[2 * nt + 1][1],
                          sb + whsw(row, gc));
                }
#pragma unroll
                for (int mi = 0; mi < 2; mi++)
#pragma unroll
                    for (int ni = 0; ni < 4; ni++) MMA_BF16(acc[mi][ni], a[mi], b[ni]);
            }
        }

        // scatter acc -> pre-tile [128][64], stride 65
        const int lr = lane >> 2, lc = lane & 3;
#pragma unroll
        for (int mi = 0; mi < 2; mi++)
#pragma unroll
            for (int ni = 0; ni < 4; ni++) {
                int r = wm * 32 + mi * 16 + lr;
                int cc = wn * 32 + ni * 8 + 2 * lc;
                pre[r * 65 + cc]           = acc[mi][ni][0];
                pre[r * 65 + cc + 1]       = acc[mi][ni][1];
                pre[(r + 8) * 65 + cc]     = acc[mi][ni][2];
                pre[(r + 8) * 65 + cc + 1] = acc[mi][ni][3];
            }
        __syncthreads();

        // fused LSTM elementwise: 8 (b,j) pairs per thread (gx bf16 from smem)
#pragma unroll
        for (int s = 0; s < 8; s++) {
            int p = s * 256 + tid;
            int r = p >> 4, jj = p & 15;
            int b = m0 + r;
            const __nv_bfloat162* g2 = reinterpret_cast<const __nv_bfloat162*>(
                smem + GX_OFF + r * GX_STRIDE_B + 8 * jj);
            float2 ga = __bfloat1622float2(g2[0]);
            float2 gb = __bfloat1622float2(g2[1]);
            float p0 = pre[r * 65 + 4 * jj + 0] + ga.x;
            float p1 = pre[r * 65 + 4 * jj + 1] + ga.y;
            float p2 = pre[r * 65 + 4 * jj + 2] + gb.x;
            float p3 = pre[r * 65 + 4 * jj + 3] + gb.y;
            float ig = sigm(p0);
            float fg = sigm(p1);
            float gg = tanhff(p2);
            float og = sigm(p3);
            float cn = fg * creg[s] + ig * gg;
            creg[s] = cn;
            hout[b * HID + (n0 >> 2) + jj] = __float2bfloat16_rn(og * tanhff(cn));
        }

        // ---- per-m-group grid barrier: bar.sync -> release-add -> acquire poll ----
        __syncthreads();                    // all h stores issued; gxs reads done
        if (t + 1 < SEQT) prefetch_gx(t + 1);   // h-independent; overlaps the wait
        CP_COMMIT();
        if (tid == 0) {
            unsigned target = (unsigned)(t + 1) * 64u;
            asm volatile("red.release.gpu.global.add.u32 [%0], %1;"
                         :: "l"(&g_barg[grp]), "r"(1u) : "memory");
            unsigned v;
            do {
                asm volatile("ld.acquire.gpu.global.u32 %0, [%1];"
                             : "=r"(v) : "l"(&g_barg[grp]) : "memory");
            } while (v < target);
        }
        __syncthreads();
    }

    // ======== fused final FC + log_softmax (after t=127 group barrier) ========
    // Each CTA handles 2 batch rows of its own m-group: b = m0 + 2*bx + {0,1}.
    {
        const __nv_bfloat16* __restrict__ hf = g_h[0];   // t=127 wrote buffer 0
        float* hrow = (float*)(smem + A_OFF);            // 2 x 1024 f32 = 8KB
        float* lg   = (float*)(smem + A_OFF + 8192);     // 2 x 32 logits
        const int bx = blockIdx.x;
#pragma unroll
        for (int rr = 0; rr < 2; rr++) {
            int b = m0 + 2 * bx + rr;
            for (int i = tid; i < HID; i += 256)
                hrow[rr * 1024 + i] = __bfloat162float(hf[(size_t)b * HID + i]);
        }
        __syncthreads();

        // 8 warps x 4 outputs = 32 outputs, each for both rows
#pragma unroll
        for (int rr = 0; rr < 2; rr++) {
#pragma unroll
            for (int oo = 0; oo < 4; oo++) {
                int o = wid * 4 + oo;
                const float* w = wfc + (size_t)o * HID;
                float s = 0.f;
                for (int k = lane; k < HID; k += 32) s += hrow[rr * 1024 + k] * w[k];
#pragma unroll
                for (int off = 16; off; off >>= 1) s += __shfl_xor_sync(0xffffffffu, s, off);
                if (lane == 0) lg[rr * 32 + o] = s;
            }
        }
        __syncthreads();

        if (tid < 64) {                     // warp 0 -> row 0, warp 1 -> row 1
            int rr = tid >> 5, oi = tid & 31;
            float l = lg[rr * 32 + oi];
            float m = l;
#pragma unroll
            for (int off = 16; off; off >>= 1) m = fmaxf(m, __shfl_xor_sync(0xffffffffu, m, off));
            float e = expf(l - m);
            float se = e;
#pragma unroll
            for (int off = 16; off; off >>= 1) se += __shfl_xor_sync(0xffffffffu, se, off);
            out[(m0 + 2 * bx + rr) * NOUT + oi] = l - m - logf(se);
        }
    }
}

// ---------------- launch ----------------
extern "C" void kernel_launch(void* const* d_in, const int* in_sizes, int n_in,
                              void* d_out, int out_size) {
    const float* x    = (const float*)d_in[0];
    const float* w_ii = (const float*)d_in[1];
    const float* w_hi = (const float*)d_in[2];
    const float* b_ii = (const float*)d_in[3];
    const float* b_hi = (const float*)d_in[4];
    const float* w_if = (const float*)d_in[5];
    const float* w_hf = (const float*)d_in[6];
    const float* b_if = (const float*)d_in[7];
    const float* b_hf = (const float*)d_in[8];
    const float* w_io = (const float*)d_in[9];
    const float* w_ho = (const float*)d_in[10];
    const float* b_io = (const float*)d_in[11];
    const float* b_ho = (const float*)d_in[12];
    const float* w_ic = (const float*)d_in[13];
    const float* w_hc = (const float*)d_in[14];
    const float* b_ic = (const float*)d_in[15];
    const float* b_hc = (const float*)d_in[16];
    const float* w_fc = (const float*)d_in[17];

    cudaFuncSetAttribute(k_gemm_x, cudaFuncAttributeMaxDynamicSharedMemorySize, X_SMEM);
    cudaFuncSetAttribute(k_steps,  cudaFuncAttributeMaxDynamicSharedMemorySize, S_SMEM);

    k_prep<<<2048, 256>>>(x, w_ii, w_if, w_ic, w_io, w_hi, w_hf, w_hc, w_ho,
                          b_ii, b_hi, b_if, b_hf, b_ic, b_hc, b_io, b_ho);

    k_gemm_x<<<dim3(32, 256), 256, X_SMEM>>>();

    k_steps<<<dim3(64, 2), 256, S_SMEM>>>(w_fc, (float*)d_out);
}